// round 15
// baseline (speedup 1.0000x reference)
#include <cuda_runtime.h>

#define EPS 1e-10f
#define NSTATE 68
#define NF4 17                      // 68 floats = 17 float4
#define COLSTRIDE 33                // 33 % 8 == 1 -> conflict-free bank walk
#define WARPS_PER_BLOCK 4
#define THREADS (WARPS_PER_BLOCK * 32)

// Parameters baked into the constant bank at compile time (verified at runtime,
// once per block, overlapped with the tile loads). [0..74] = PARAM_DEFAULTS.
// [75..80] = derived constants (fp32-folded identically to the runtime fallback).
__constant__ float c_p[81] = {
    0.1f,0.05f,0.2f,0.1f,0.1f,0.1f,0.01f,0.01f,0.05f,0.01f,
    0.1f,0.01f,0.1f,0.01f,0.01f,0.01f,
    0.01f,0.01f,0.05f,0.01f,0.01f,0.01f,0.1f,0.1f,
    0.01f,0.01f,0.01f,0.1f,0.1f,0.05f,0.01f,
    0.05f,0.05f,0.1f,0.1f,0.1f,0.1f,
    0.05f,0.1f,0.01f,0.1f,0.05f,0.1f,0.01f,
    0.05f,0.05f,0.1f,0.05f,0.1f,0.05f,0.1f,0.1f,
    0.05f,0.1f,1.0f,1.0f,1.0f,1.0f,0.1f,0.05f,
    0.1f,1.0f,1.0f,0.05f,0.1f,0.1f,0.05f,
    0.05f,0.02f,0.01f,0.02f,0.02f,
    0.01f,0.05f,0.03f,
    // derived:
    0.1f * 1.0f / (1.0f + 1.0f + 1e-10f),   // 75 kBRAF_eff = 0.05
    1.0f / (1.0f + 0.1f + 1e-10f),          // 76 tram_ksr (Tram = 0.1)
    0.1f / (0.1f + 1e-10f),                 // 77 kmDuspRatio
    0.1f / (0.1f + 1e-10f),                 // 78 kmSprtyRatio
    0.1f * 1.0f,                            // 79 kDimVem
    0.1f * 1.0f                             // 80 kParaVem
};

// ---- FAST PATH: params from the statically-initialized constant bank ----
__device__ __forceinline__ void compute_rhs_const(const float* ys, float* d) {
    const float ka1 = c_p[0], kr1 = c_p[1], kc1 = c_p[2];
    const float kBRAF_eff    = c_p[75];
    const float tram_ksr     = c_p[76];
    const float kmDuspRatio  = c_p[77];
    const float kmSprtyRatio = c_p[78];
    const float kDimVem      = c_p[79];
    const float kParaVem     = c_p[80];

    d[0] = -ka1*ys[0] + kr1*ys[1];
    d[1] =  ka1*ys[0] - kr1*ys[1] - kc1*ys[1];
    d[2] =  kc1*ys[1] - c_p[6]*ys[2] - c_p[7]*ys[28]*ys[2];
    d[3] = -c_p[31]*ys[3] + kr1*ys[4];
    d[4] =  c_p[31]*ys[3] - kr1*ys[4] - kc1*ys[4];
    d[5] =  kc1*ys[4] - c_p[6]*ys[5] - c_p[7]*ys[28]*ys[5];
    d[6] = -c_p[32]*ys[6] + kr1*ys[7];
    d[7] =  c_p[32]*ys[6] - kr1*ys[7] - kc1*ys[7];
    d[8] =  kc1*ys[7] - c_p[6]*ys[8] - c_p[7]*ys[28]*ys[8];

    float a29 = ka1*ys[2]*ys[9];
    d[9]  = -a29;
    d[10] =  a29 - c_p[8]*ys[11]*ys[10];
    d[11] = -c_p[9]*ys[10]*ys[11];
    d[12] =  c_p[10]*ys[10]*ys[2] - c_p[11]*ys[26]*ys[12];
    d[13] =  c_p[12]*ys[12]*ys[10] - c_p[13]*ys[24]*ys[13];
    float s14 = ka1*ys[13]*ys[14];
    d[14] = -s14;
    d[15] =  s14;
    float s16 = ka1*ys[13]*ys[16];
    d[16] = -s16;
    d[17] =  s16;
    float s18 = ka1*ys[13]*ys[18];
    float s19 = ka1*ys[19]*ys[20];
    d[18] = -s18;
    d[19] =  s18 - s19;
    d[20] = -s19;

    float paradox   = kParaVem * ys[61];
    float akt_craf  = c_p[70]*ys[52]*ys[21];
    float dimF      = kDimVem*ys[24]*ys[21];
    float dimD      = c_p[59]*ys[61];
    float craf_fwd  = c_p[3]*ys[19]*ys[21];
    float craf_rev  = c_p[14]*ys[28]*ys[22];
    float craf_deg  = c_p[15]*ys[22]*ys[35];
    float braf_act  = kBRAF_eff*ys[23]*ys[19];
    d[21] = -craf_fwd + craf_rev + craf_deg - dimF + dimD - akt_craf;
    d[22] =  craf_fwd - craf_rev - craf_deg + paradox;
    d[23] = -braf_act - dimF + dimD;
    d[24] =  braf_act - c_p[20]*ys[24] - dimF + dimD;
    d[61] =  dimF - dimD - c_p[15]*ys[61]*ys[35];

    float raf_to_mek = c_p[4]*ys[22] + c_p[50]*ys[24] + c_p[51]*ys[22];
    float ksr_to_mek = c_p[52]*ys[60];
    float mek_fwd    = (raf_to_mek + ksr_to_mek)*ys[25];
    float mek_rev    = c_p[16]*ys[28]*ys[26];
    float mek_deg    = c_p[17]*ys[26]*ys[34];
    d[25] = -mek_fwd + mek_rev + mek_deg;
    d[26] =  mek_fwd - mek_rev - mek_deg;
    float erk_fwd = c_p[5]*ys[26]*ys[27];
    float erk_bk  = c_p[18]*ys[30]*ys[28] + c_p[19]*ys[28]*ys[33] + c_p[29]*ys[30]*ys[28];
    d[27] = -erk_fwd + erk_bk;
    d[28] =  erk_fwd - erk_bk;

    float denom_dusp = 1.0f + kmDuspRatio*ys[28];
    d[29] = c_p[27]*ys[28]/(denom_dusp + EPS) - c_p[21]*ys[29]*ys[36] - c_p[30]*ys[29]*ys[28];
    d[30] = -c_p[21]*ys[29]*ys[30];
    float denom_spry = 1.0f + kmSprtyRatio*ys[28];
    float spry_dn = c_p[24]*ys[31]*ys[32];
    d[31] = c_p[28]*ys[28]/(denom_spry + EPS) - spry_dn;
    d[32] = -spry_dn;
    d[33] = -c_p[19]*ys[28]*ys[33];
    d[34] = -mek_deg;
    d[35] = -craf_deg;
    d[36] = -c_p[21]*ys[29]*ys[36];

    d[37] = -ka1*ys[37] + kr1*ys[38];
    d[38] =  ka1*ys[37] - kr1*ys[38] - kc1*ys[38];
    d[39] =  kc1*ys[38] - c_p[7]*ys[28]*ys[39];
    float erk_irs = c_p[68]*ys[28]*ys[41];
    float s6k_irs = c_p[71]*ys[66]*ys[41];
    float irs_fwd = ka1*ys[2]*ys[40];
    d[40] = -irs_fwd + erk_irs + s6k_irs;
    d[41] =  irs_fwd - erk_irs - s6k_irs;

    float gab1 = 1.0f / (1.0f + c_p[72]*ys[28]);
    float bE  = c_p[33]*ys[2]*ys[42]*gab1;
    float bH2 = c_p[34]*ys[5]*ys[42]*gab1;
    float bH3 = c_p[35]*ys[8]*ys[42]*gab1;
    float bI  = c_p[36]*ys[39]*ys[42];
    float bP  = c_p[64]*ys[64]*ys[42];
    float sum_p85c = ys[43] + ys[44] + ys[45] + ys[46] + ys[67];
    float kunb = c_p[37];
    d[42] = -bE - bH2 - bH3 - bI - bP + kunb*sum_p85c;
    d[43] = bE  - kunb*ys[43];
    d[44] = bH2 - kunb*ys[44];
    d[45] = bH3 - kunb*ys[45];
    d[46] = bI  - kunb*ys[46];
    d[67] = bP  - kunb*ys[67];

    float pi3k_act = c_p[38]*sum_p85c*ys[47] + c_p[67]*ys[15]*ys[47];
    float mtor_fb  = c_p[39]*ys[56]*ys[48];
    d[47] = -pi3k_act + mtor_fb;
    d[48] =  pi3k_act - mtor_fb;
    float pip_fwd = c_p[40]*ys[48]*ys[49];
    float pip_rev = c_p[41]*ys[51]*ys[50];
    d[49] = -pip_fwd + pip_rev;
    d[50] =  pip_fwd - pip_rev;
    d[51] = c_p[69]*ys[28] - c_p[25]*ys[51];
    float akt_fwd = c_p[42]*ys[50]*ys[53];
    float akt_rev = c_p[43]*ys[52];
    d[52] =  akt_fwd - akt_rev;
    d[53] = -akt_fwd + akt_rev;
    float tsc = c_p[73]*ys[52]*ys[54];
    d[54] = -tsc;
    d[55] =  tsc - c_p[25]*ys[55];
    float mtor_fwd = c_p[44]*ys[52]*ys[57];
    float mtor_rev = c_p[45]*ys[56];
    d[56] =  mtor_fwd - mtor_rev;
    d[57] = -mtor_fwd + mtor_rev;
    float ebp_fwd = c_p[46]*ys[56]*ys[58];
    float ebp_rev = c_p[47]*ys[59];
    d[58] = -ebp_fwd + ebp_rev;
    d[59] =  ebp_fwd - ebp_rev;

    float ksr_fwd = c_p[48]*ys[19]*ys[62]*tram_ksr;
    float ksr_rev = c_p[49]*ys[60];
    d[60] =  ksr_fwd - ksr_rev;
    d[62] = -ksr_fwd + ksr_rev;

    d[63] = -c_p[63]*ys[63];
    d[64] =  c_p[63]*ys[63] - c_p[6]*ys[64];

    float s6_fwd = c_p[65]*ys[56]*ys[65];
    float rsk    = c_p[74]*ys[28]*ys[65];
    float s6_rev = c_p[66]*ys[66];
    d[65] = -s6_fwd + s6_rev - rsk;
    d[66] =  s6_fwd - s6_rev + rsk;
}

// ---- GENERIC FALLBACK: params from global memory (taken only if params differ) ----
__device__ __noinline__ void compute_rhs_gen(const float* __restrict__ p,
                                             const float* ys, float* d) {
    const float ic50n     = __powf(p[61], p[62]);
    const float vemn      = __powf(p[57], p[62]);
    const float kBRAF_eff = p[0] * ic50n / (ic50n + vemn + EPS);
    const float ktn       = __powf(p[55], p[56]);
    const float tn        = __powf(p[53], p[56]);
    const float tram_ksr  = ktn / (ktn + tn + EPS);
    const float kmDuspRatio  = p[27] / (p[22] + EPS);
    const float kmSprtyRatio = p[28] / (p[23] + EPS);
    const float kDimVem   = p[58] * p[57];
    const float kParaVem  = p[60] * p[57];

    d[0] = -p[0]*ys[0] + p[1]*ys[1];
    d[1] =  p[0]*ys[0] - p[1]*ys[1] - p[2]*ys[1];
    d[2] =  p[2]*ys[1] - p[6]*ys[2] - p[7]*ys[28]*ys[2];
    d[3] = -p[31]*ys[3] + p[1]*ys[4];
    d[4] =  p[31]*ys[3] - p[1]*ys[4] - p[2]*ys[4];
    d[5] =  p[2]*ys[4] - p[6]*ys[5] - p[7]*ys[28]*ys[5];
    d[6] = -p[32]*ys[6] + p[1]*ys[7];
    d[7] =  p[32]*ys[6] - p[1]*ys[7] - p[2]*ys[7];
    d[8] =  p[2]*ys[7] - p[6]*ys[8] - p[7]*ys[28]*ys[8];
    float a29 = p[0]*ys[2]*ys[9];
    d[9]  = -a29;
    d[10] =  a29 - p[8]*ys[11]*ys[10];
    d[11] = -p[9]*ys[10]*ys[11];
    d[12] =  p[10]*ys[10]*ys[2] - p[11]*ys[26]*ys[12];
    d[13] =  p[12]*ys[12]*ys[10] - p[13]*ys[24]*ys[13];
    float s14 = p[0]*ys[13]*ys[14];
    d[14] = -s14;  d[15] = s14;
    float s16 = p[0]*ys[13]*ys[16];
    d[16] = -s16;  d[17] = s16;
    float s18 = p[0]*ys[13]*ys[18];
    float s19 = p[0]*ys[19]*ys[20];
    d[18] = -s18;  d[19] = s18 - s19;  d[20] = -s19;
    float paradox   = kParaVem * ys[61];
    float akt_craf  = p[70]*ys[52]*ys[21];
    float dimF      = kDimVem*ys[24]*ys[21];
    float dimD      = p[59]*ys[61];
    float craf_fwd  = p[3]*ys[19]*ys[21];
    float craf_rev  = p[14]*ys[28]*ys[22];
    float craf_deg  = p[15]*ys[22]*ys[35];
    float braf_act  = kBRAF_eff*ys[23]*ys[19];
    d[21] = -craf_fwd + craf_rev + craf_deg - dimF + dimD - akt_craf;
    d[22] =  craf_fwd - craf_rev - craf_deg + paradox;
    d[23] = -braf_act - dimF + dimD;
    d[24] =  braf_act - p[20]*ys[24] - dimF + dimD;
    d[61] =  dimF - dimD - p[15]*ys[61]*ys[35];
    float raf_to_mek = p[4]*ys[22] + p[50]*ys[24] + p[51]*ys[22];
    float ksr_to_mek = p[52]*ys[60];
    float mek_fwd    = (raf_to_mek + ksr_to_mek)*ys[25];
    float mek_rev    = p[16]*ys[28]*ys[26];
    float mek_deg    = p[17]*ys[26]*ys[34];
    d[25] = -mek_fwd + mek_rev + mek_deg;
    d[26] =  mek_fwd - mek_rev - mek_deg;
    float erk_fwd = p[5]*ys[26]*ys[27];
    float erk_bk  = p[18]*ys[30]*ys[28] + p[19]*ys[28]*ys[33] + p[29]*ys[30]*ys[28];
    d[27] = -erk_fwd + erk_bk;
    d[28] =  erk_fwd - erk_bk;
    float denom_dusp = 1.0f + kmDuspRatio*ys[28];
    d[29] = p[27]*ys[28]/(denom_dusp + EPS) - p[21]*ys[29]*ys[36] - p[30]*ys[29]*ys[28];
    d[30] = -p[21]*ys[29]*ys[30];
    float denom_spry = 1.0f + kmSprtyRatio*ys[28];
    float spry_dn = p[24]*ys[31]*ys[32];
    d[31] = p[28]*ys[28]/(denom_spry + EPS) - spry_dn;
    d[32] = -spry_dn;
    d[33] = -p[19]*ys[28]*ys[33];
    d[34] = -mek_deg;
    d[35] = -craf_deg;
    d[36] = -p[21]*ys[29]*ys[36];
    d[37] = -p[0]*ys[37] + p[1]*ys[38];
    d[38] =  p[0]*ys[37] - p[1]*ys[38] - p[2]*ys[38];
    d[39] =  p[2]*ys[38] - p[7]*ys[28]*ys[39];
    float erk_irs = p[68]*ys[28]*ys[41];
    float s6k_irs = p[71]*ys[66]*ys[41];
    float irs_fwd = p[0]*ys[2]*ys[40];
    d[40] = -irs_fwd + erk_irs + s6k_irs;
    d[41] =  irs_fwd - erk_irs - s6k_irs;
    float gab1 = 1.0f / (1.0f + p[72]*ys[28]);
    float bE  = p[33]*ys[2]*ys[42]*gab1;
    float bH2 = p[34]*ys[5]*ys[42]*gab1;
    float bH3 = p[35]*ys[8]*ys[42]*gab1;
    float bI  = p[36]*ys[39]*ys[42];
    float bP  = p[64]*ys[64]*ys[42];
    float sum_p85c = ys[43] + ys[44] + ys[45] + ys[46] + ys[67];
    float kunb = p[37];
    d[42] = -bE - bH2 - bH3 - bI - bP + kunb*sum_p85c;
    d[43] = bE  - kunb*ys[43];
    d[44] = bH2 - kunb*ys[44];
    d[45] = bH3 - kunb*ys[45];
    d[46] = bI  - kunb*ys[46];
    d[67] = bP  - kunb*ys[67];
    float pi3k_act = p[38]*sum_p85c*ys[47] + p[67]*ys[15]*ys[47];
    float mtor_fb  = p[39]*ys[56]*ys[48];
    d[47] = -pi3k_act + mtor_fb;
    d[48] =  pi3k_act - mtor_fb;
    float pip_fwd = p[40]*ys[48]*ys[49];
    float pip_rev = p[41]*ys[51]*ys[50];
    d[49] = -pip_fwd + pip_rev;
    d[50] =  pip_fwd - pip_rev;
    d[51] = p[69]*ys[28] - p[25]*ys[51];
    float akt_fwd = p[42]*ys[50]*ys[53];
    float akt_rev = p[43]*ys[52];
    d[52] =  akt_fwd - akt_rev;
    d[53] = -akt_fwd + akt_rev;
    float tsc = p[73]*ys[52]*ys[54];
    d[54] = -tsc;
    d[55] =  tsc - p[25]*ys[55];
    float mtor_fwd = p[44]*ys[52]*ys[57];
    float mtor_rev = p[45]*ys[56];
    d[56] =  mtor_fwd - mtor_rev;
    d[57] = -mtor_fwd + mtor_rev;
    float ebp_fwd = p[46]*ys[56]*ys[58];
    float ebp_rev = p[47]*ys[59];
    d[58] = -ebp_fwd + ebp_rev;
    d[59] =  ebp_fwd - ebp_rev;
    float ksr_fwd = p[48]*ys[19]*ys[62]*tram_ksr;
    float ksr_rev = p[49]*ys[60];
    d[60] =  ksr_fwd - ksr_rev;
    d[62] = -ksr_fwd + ksr_rev;
    d[63] = -p[63]*ys[63];
    d[64] =  p[63]*ys[63] - p[6]*ys[64];
    float s6_fwd = p[65]*ys[56]*ys[65];
    float rsk    = p[74]*ys[28]*ys[65];
    float s6_rev = p[66]*ys[66];
    d[65] = -s6_fwd + s6_rev - rsk;
    d[66] =  s6_fwd - s6_rev + rsk;
}

__global__ __launch_bounds__(THREADS, 4)
void mapk_rhs_kernel(const float* __restrict__ y, const float* __restrict__ params,
                     float* __restrict__ out, int n) {
    // Per-warp float4 tile, column-major with stride 33 (conflict-free).
    __shared__ float4 stage[WARPS_PER_BLOCK][NF4 * COLSTRIDE];
    __shared__ int sFast;

    const int tid  = threadIdx.x;
    const int lane = tid & 31;
    const int warp = tid >> 5;

    if (tid == 0) sFast = 1;
    __syncthreads();                       // cheap: no memory dependencies yet

    const int rowStart = blockIdx.x * THREADS + warp * 32;
    const int rowsHere = (rowStart < n) ? min(32, n - rowStart) : 0;
    const bool fullTile = (rowsHere == 32);

    float4* sm = stage[warp];

    // ---- Phase 1: tile loads issued FIRST (front-batched, high MLP) ----
    if (fullTile) {
        const float4* gsrc = reinterpret_cast<const float4*>(y) + (size_t)rowStart * NF4;
        #pragma unroll
        for (int j = 0; j < NF4; j++) {
            int i = j * 32 + lane;          // f4 index within warp tile
            int r = i / NF4;
            int c = i - r * NF4;
            float4 v = __ldg(&gsrc[i]);
            v.x = fmaxf(v.x, 0.0f);
            v.y = fmaxf(v.y, 0.0f);
            v.z = fmaxf(v.z, 0.0f);
            v.w = fmaxf(v.w, 0.0f);
            sm[c * COLSTRIDE + r] = v;
        }
    } else if (lane < rowsHere) {
        // tail: each active lane loads its own row into its tile column slots
        const float4* yv = reinterpret_cast<const float4*>(y) + (size_t)(rowStart + lane) * NF4;
        #pragma unroll
        for (int c = 0; c < NF4; c++) {
            float4 v = __ldg(&yv[c]);
            v.x = fmaxf(v.x, 0.0f);
            v.y = fmaxf(v.y, 0.0f);
            v.z = fmaxf(v.z, 0.0f);
            v.w = fmaxf(v.w, 0.0f);
            sm[c * COLSTRIDE + lane] = v;
        }
    }

    // ---- Param verification, overlapped with the tile loads above ----
    if (tid < 75) {
        if (__ldg(&params[tid]) != c_p[tid]) sFast = 0;   // benign race: all write 0
    }
    __syncthreads();                       // covers smem tiles + sFast
    const bool fast = (sFast != 0);

    if (rowsHere == 0) return;

    // ---- Phase 2: each thread owns row = lane; conflict-free smem access ----
    if (lane < rowsHere) {
        float ys[NSTATE];
        float4* ysv = reinterpret_cast<float4*>(ys);
        #pragma unroll
        for (int c = 0; c < NF4; c++) ysv[c] = sm[c * COLSTRIDE + lane];

        float d[NSTATE];
        if (fast) compute_rhs_const(ys, d);
        else      compute_rhs_gen(params, ys, d);

        const float4* dv = reinterpret_cast<const float4*>(d);
        #pragma unroll
        for (int c = 0; c < NF4; c++) sm[c * COLSTRIDE + lane] = dv[c];
    }
    __syncwarp();

    // ---- Phase 3: coalesced streaming stores (evict-first: output never re-read) ----
    if (fullTile) {
        float4* gdst = reinterpret_cast<float4*>(out) + (size_t)rowStart * NF4;
        #pragma unroll
        for (int j = 0; j < NF4; j++) {
            int i = j * 32 + lane;
            int r = i / NF4;
            int c = i - r * NF4;
            __stcs(&gdst[i], sm[c * COLSTRIDE + r]);
        }
    } else if (lane < rowsHere) {
        float4* ov = reinterpret_cast<float4*>(out) + (size_t)(rowStart + lane) * NF4;
        #pragma unroll
        for (int c = 0; c < NF4; c++) __stcs(&ov[c], sm[c * COLSTRIDE + lane]);
    }
}

extern "C" void kernel_launch(void* const* d_in, const int* in_sizes, int n_in,
                              void* d_out, int out_size) {
    // inputs per metadata order: t (1), y (B*68), params (75)
    const float* y      = (const float*)d_in[1];
    const float* params = (const float*)d_in[2];
    float* out = (float*)d_out;

    int n = in_sizes[1] / NSTATE;   // number of rows (B)

    int blocks = (n + THREADS - 1) / THREADS;
    mapk_rhs_kernel<<<blocks, THREADS>>>(y, params, out, n);
}

// round 16
// speedup vs baseline: 1.4246x; 1.4246x over previous
#include <cuda_runtime.h>

#define EPS 1e-10f
#define NSTATE 68
#define NF4 17                      // 68 floats = 17 float4
#define COLSTRIDE 33                // 33 % 8 == 1 -> conflict-free bank walk
#define WARPS_PER_BLOCK 4
#define THREADS (WARPS_PER_BLOCK * 32)

// Parameters baked into the constant bank at compile time (verified at runtime,
// once per block). [0..74] = PARAM_DEFAULTS. [75..80] = derived constants
// (fp32-folded identically to the runtime fallback).
__constant__ float c_p[81] = {
    0.1f,0.05f,0.2f,0.1f,0.1f,0.1f,0.01f,0.01f,0.05f,0.01f,
    0.1f,0.01f,0.1f,0.01f,0.01f,0.01f,
    0.01f,0.01f,0.05f,0.01f,0.01f,0.01f,0.1f,0.1f,
    0.01f,0.01f,0.01f,0.1f,0.1f,0.05f,0.01f,
    0.05f,0.05f,0.1f,0.1f,0.1f,0.1f,
    0.05f,0.1f,0.01f,0.1f,0.05f,0.1f,0.01f,
    0.05f,0.05f,0.1f,0.05f,0.1f,0.05f,0.1f,0.1f,
    0.05f,0.1f,1.0f,1.0f,1.0f,1.0f,0.1f,0.05f,
    0.1f,1.0f,1.0f,0.05f,0.1f,0.1f,0.05f,
    0.05f,0.02f,0.01f,0.02f,0.02f,
    0.01f,0.05f,0.03f,
    // derived:
    0.1f * 1.0f / (1.0f + 1.0f + 1e-10f),   // 75 kBRAF_eff = 0.05
    1.0f / (1.0f + 0.1f + 1e-10f),          // 76 tram_ksr (Tram = 0.1)
    0.1f / (0.1f + 1e-10f),                 // 77 kmDuspRatio
    0.1f / (0.1f + 1e-10f),                 // 78 kmSprtyRatio
    0.1f * 1.0f,                            // 79 kDimVem
    0.1f * 1.0f                             // 80 kParaVem
};

// ---- FAST PATH: params from the statically-initialized constant bank ----
__device__ __forceinline__ void compute_rhs_const(const float* ys, float* d) {
    const float ka1 = c_p[0], kr1 = c_p[1], kc1 = c_p[2];
    const float kBRAF_eff    = c_p[75];
    const float tram_ksr     = c_p[76];
    const float kmDuspRatio  = c_p[77];
    const float kmSprtyRatio = c_p[78];
    const float kDimVem      = c_p[79];
    const float kParaVem     = c_p[80];

    d[0] = -ka1*ys[0] + kr1*ys[1];
    d[1] =  ka1*ys[0] - kr1*ys[1] - kc1*ys[1];
    d[2] =  kc1*ys[1] - c_p[6]*ys[2] - c_p[7]*ys[28]*ys[2];
    d[3] = -c_p[31]*ys[3] + kr1*ys[4];
    d[4] =  c_p[31]*ys[3] - kr1*ys[4] - kc1*ys[4];
    d[5] =  kc1*ys[4] - c_p[6]*ys[5] - c_p[7]*ys[28]*ys[5];
    d[6] = -c_p[32]*ys[6] + kr1*ys[7];
    d[7] =  c_p[32]*ys[6] - kr1*ys[7] - kc1*ys[7];
    d[8] =  kc1*ys[7] - c_p[6]*ys[8] - c_p[7]*ys[28]*ys[8];

    float a29 = ka1*ys[2]*ys[9];
    d[9]  = -a29;
    d[10] =  a29 - c_p[8]*ys[11]*ys[10];
    d[11] = -c_p[9]*ys[10]*ys[11];
    d[12] =  c_p[10]*ys[10]*ys[2] - c_p[11]*ys[26]*ys[12];
    d[13] =  c_p[12]*ys[12]*ys[10] - c_p[13]*ys[24]*ys[13];
    float s14 = ka1*ys[13]*ys[14];
    d[14] = -s14;
    d[15] =  s14;
    float s16 = ka1*ys[13]*ys[16];
    d[16] = -s16;
    d[17] =  s16;
    float s18 = ka1*ys[13]*ys[18];
    float s19 = ka1*ys[19]*ys[20];
    d[18] = -s18;
    d[19] =  s18 - s19;
    d[20] = -s19;

    float paradox   = kParaVem * ys[61];
    float akt_craf  = c_p[70]*ys[52]*ys[21];
    float dimF      = kDimVem*ys[24]*ys[21];
    float dimD      = c_p[59]*ys[61];
    float craf_fwd  = c_p[3]*ys[19]*ys[21];
    float craf_rev  = c_p[14]*ys[28]*ys[22];
    float craf_deg  = c_p[15]*ys[22]*ys[35];
    float braf_act  = kBRAF_eff*ys[23]*ys[19];
    d[21] = -craf_fwd + craf_rev + craf_deg - dimF + dimD - akt_craf;
    d[22] =  craf_fwd - craf_rev - craf_deg + paradox;
    d[23] = -braf_act - dimF + dimD;
    d[24] =  braf_act - c_p[20]*ys[24] - dimF + dimD;
    d[61] =  dimF - dimD - c_p[15]*ys[61]*ys[35];

    float raf_to_mek = c_p[4]*ys[22] + c_p[50]*ys[24] + c_p[51]*ys[22];
    float ksr_to_mek = c_p[52]*ys[60];
    float mek_fwd    = (raf_to_mek + ksr_to_mek)*ys[25];
    float mek_rev    = c_p[16]*ys[28]*ys[26];
    float mek_deg    = c_p[17]*ys[26]*ys[34];
    d[25] = -mek_fwd + mek_rev + mek_deg;
    d[26] =  mek_fwd - mek_rev - mek_deg;
    float erk_fwd = c_p[5]*ys[26]*ys[27];
    float erk_bk  = c_p[18]*ys[30]*ys[28] + c_p[19]*ys[28]*ys[33] + c_p[29]*ys[30]*ys[28];
    d[27] = -erk_fwd + erk_bk;
    d[28] =  erk_fwd - erk_bk;

    float denom_dusp = 1.0f + kmDuspRatio*ys[28];
    d[29] = c_p[27]*ys[28]/(denom_dusp + EPS) - c_p[21]*ys[29]*ys[36] - c_p[30]*ys[29]*ys[28];
    d[30] = -c_p[21]*ys[29]*ys[30];
    float denom_spry = 1.0f + kmSprtyRatio*ys[28];
    float spry_dn = c_p[24]*ys[31]*ys[32];
    d[31] = c_p[28]*ys[28]/(denom_spry + EPS) - spry_dn;
    d[32] = -spry_dn;
    d[33] = -c_p[19]*ys[28]*ys[33];
    d[34] = -mek_deg;
    d[35] = -craf_deg;
    d[36] = -c_p[21]*ys[29]*ys[36];

    d[37] = -ka1*ys[37] + kr1*ys[38];
    d[38] =  ka1*ys[37] - kr1*ys[38] - kc1*ys[38];
    d[39] =  kc1*ys[38] - c_p[7]*ys[28]*ys[39];
    float erk_irs = c_p[68]*ys[28]*ys[41];
    float s6k_irs = c_p[71]*ys[66]*ys[41];
    float irs_fwd = ka1*ys[2]*ys[40];
    d[40] = -irs_fwd + erk_irs + s6k_irs;
    d[41] =  irs_fwd - erk_irs - s6k_irs;

    float gab1 = 1.0f / (1.0f + c_p[72]*ys[28]);
    float bE  = c_p[33]*ys[2]*ys[42]*gab1;
    float bH2 = c_p[34]*ys[5]*ys[42]*gab1;
    float bH3 = c_p[35]*ys[8]*ys[42]*gab1;
    float bI  = c_p[36]*ys[39]*ys[42];
    float bP  = c_p[64]*ys[64]*ys[42];
    float sum_p85c = ys[43] + ys[44] + ys[45] + ys[46] + ys[67];
    float kunb = c_p[37];
    d[42] = -bE - bH2 - bH3 - bI - bP + kunb*sum_p85c;
    d[43] = bE  - kunb*ys[43];
    d[44] = bH2 - kunb*ys[44];
    d[45] = bH3 - kunb*ys[45];
    d[46] = bI  - kunb*ys[46];
    d[67] = bP  - kunb*ys[67];

    float pi3k_act = c_p[38]*sum_p85c*ys[47] + c_p[67]*ys[15]*ys[47];
    float mtor_fb  = c_p[39]*ys[56]*ys[48];
    d[47] = -pi3k_act + mtor_fb;
    d[48] =  pi3k_act - mtor_fb;
    float pip_fwd = c_p[40]*ys[48]*ys[49];
    float pip_rev = c_p[41]*ys[51]*ys[50];
    d[49] = -pip_fwd + pip_rev;
    d[50] =  pip_fwd - pip_rev;
    d[51] = c_p[69]*ys[28] - c_p[25]*ys[51];
    float akt_fwd = c_p[42]*ys[50]*ys[53];
    float akt_rev = c_p[43]*ys[52];
    d[52] =  akt_fwd - akt_rev;
    d[53] = -akt_fwd + akt_rev;
    float tsc = c_p[73]*ys[52]*ys[54];
    d[54] = -tsc;
    d[55] =  tsc - c_p[25]*ys[55];
    float mtor_fwd = c_p[44]*ys[52]*ys[57];
    float mtor_rev = c_p[45]*ys[56];
    d[56] =  mtor_fwd - mtor_rev;
    d[57] = -mtor_fwd + mtor_rev;
    float ebp_fwd = c_p[46]*ys[56]*ys[58];
    float ebp_rev = c_p[47]*ys[59];
    d[58] = -ebp_fwd + ebp_rev;
    d[59] =  ebp_fwd - ebp_rev;

    float ksr_fwd = c_p[48]*ys[19]*ys[62]*tram_ksr;
    float ksr_rev = c_p[49]*ys[60];
    d[60] =  ksr_fwd - ksr_rev;
    d[62] = -ksr_fwd + ksr_rev;

    d[63] = -c_p[63]*ys[63];
    d[64] =  c_p[63]*ys[63] - c_p[6]*ys[64];

    float s6_fwd = c_p[65]*ys[56]*ys[65];
    float rsk    = c_p[74]*ys[28]*ys[65];
    float s6_rev = c_p[66]*ys[66];
    d[65] = -s6_fwd + s6_rev - rsk;
    d[66] =  s6_fwd - s6_rev + rsk;
}

// ---- GENERIC FALLBACK: params from global memory (taken only if params differ) ----
__device__ __noinline__ void compute_rhs_gen(const float* __restrict__ p,
                                             const float* ys, float* d) {
    const float ic50n     = __powf(p[61], p[62]);
    const float vemn      = __powf(p[57], p[62]);
    const float kBRAF_eff = p[0] * ic50n / (ic50n + vemn + EPS);
    const float ktn       = __powf(p[55], p[56]);
    const float tn        = __powf(p[53], p[56]);
    const float tram_ksr  = ktn / (ktn + tn + EPS);
    const float kmDuspRatio  = p[27] / (p[22] + EPS);
    const float kmSprtyRatio = p[28] / (p[23] + EPS);
    const float kDimVem   = p[58] * p[57];
    const float kParaVem  = p[60] * p[57];

    d[0] = -p[0]*ys[0] + p[1]*ys[1];
    d[1] =  p[0]*ys[0] - p[1]*ys[1] - p[2]*ys[1];
    d[2] =  p[2]*ys[1] - p[6]*ys[2] - p[7]*ys[28]*ys[2];
    d[3] = -p[31]*ys[3] + p[1]*ys[4];
    d[4] =  p[31]*ys[3] - p[1]*ys[4] - p[2]*ys[4];
    d[5] =  p[2]*ys[4] - p[6]*ys[5] - p[7]*ys[28]*ys[5];
    d[6] = -p[32]*ys[6] + p[1]*ys[7];
    d[7] =  p[32]*ys[6] - p[1]*ys[7] - p[2]*ys[7];
    d[8] =  p[2]*ys[7] - p[6]*ys[8] - p[7]*ys[28]*ys[8];
    float a29 = p[0]*ys[2]*ys[9];
    d[9]  = -a29;
    d[10] =  a29 - p[8]*ys[11]*ys[10];
    d[11] = -p[9]*ys[10]*ys[11];
    d[12] =  p[10]*ys[10]*ys[2] - p[11]*ys[26]*ys[12];
    d[13] =  p[12]*ys[12]*ys[10] - p[13]*ys[24]*ys[13];
    float s14 = p[0]*ys[13]*ys[14];
    d[14] = -s14;  d[15] = s14;
    float s16 = p[0]*ys[13]*ys[16];
    d[16] = -s16;  d[17] = s16;
    float s18 = p[0]*ys[13]*ys[18];
    float s19 = p[0]*ys[19]*ys[20];
    d[18] = -s18;  d[19] = s18 - s19;  d[20] = -s19;
    float paradox   = kParaVem * ys[61];
    float akt_craf  = p[70]*ys[52]*ys[21];
    float dimF      = kDimVem*ys[24]*ys[21];
    float dimD      = p[59]*ys[61];
    float craf_fwd  = p[3]*ys[19]*ys[21];
    float craf_rev  = p[14]*ys[28]*ys[22];
    float craf_deg  = p[15]*ys[22]*ys[35];
    float braf_act  = kBRAF_eff*ys[23]*ys[19];
    d[21] = -craf_fwd + craf_rev + craf_deg - dimF + dimD - akt_craf;
    d[22] =  craf_fwd - craf_rev - craf_deg + paradox;
    d[23] = -braf_act - dimF + dimD;
    d[24] =  braf_act - p[20]*ys[24] - dimF + dimD;
    d[61] =  dimF - dimD - p[15]*ys[61]*ys[35];
    float raf_to_mek = p[4]*ys[22] + p[50]*ys[24] + p[51]*ys[22];
    float ksr_to_mek = p[52]*ys[60];
    float mek_fwd    = (raf_to_mek + ksr_to_mek)*ys[25];
    float mek_rev    = p[16]*ys[28]*ys[26];
    float mek_deg    = p[17]*ys[26]*ys[34];
    d[25] = -mek_fwd + mek_rev + mek_deg;
    d[26] =  mek_fwd - mek_rev - mek_deg;
    float erk_fwd = p[5]*ys[26]*ys[27];
    float erk_bk  = p[18]*ys[30]*ys[28] + p[19]*ys[28]*ys[33] + p[29]*ys[30]*ys[28];
    d[27] = -erk_fwd + erk_bk;
    d[28] =  erk_fwd - erk_bk;
    float denom_dusp = 1.0f + kmDuspRatio*ys[28];
    d[29] = p[27]*ys[28]/(denom_dusp + EPS) - p[21]*ys[29]*ys[36] - p[30]*ys[29]*ys[28];
    d[30] = -p[21]*ys[29]*ys[30];
    float denom_spry = 1.0f + kmSprtyRatio*ys[28];
    float spry_dn = p[24]*ys[31]*ys[32];
    d[31] = p[28]*ys[28]/(denom_spry + EPS) - spry_dn;
    d[32] = -spry_dn;
    d[33] = -p[19]*ys[28]*ys[33];
    d[34] = -mek_deg;
    d[35] = -craf_deg;
    d[36] = -p[21]*ys[29]*ys[36];
    d[37] = -p[0]*ys[37] + p[1]*ys[38];
    d[38] =  p[0]*ys[37] - p[1]*ys[38] - p[2]*ys[38];
    d[39] =  p[2]*ys[38] - p[7]*ys[28]*ys[39];
    float erk_irs = p[68]*ys[28]*ys[41];
    float s6k_irs = p[71]*ys[66]*ys[41];
    float irs_fwd = p[0]*ys[2]*ys[40];
    d[40] = -irs_fwd + erk_irs + s6k_irs;
    d[41] =  irs_fwd - erk_irs - s6k_irs;
    float gab1 = 1.0f / (1.0f + p[72]*ys[28]);
    float bE  = p[33]*ys[2]*ys[42]*gab1;
    float bH2 = p[34]*ys[5]*ys[42]*gab1;
    float bH3 = p[35]*ys[8]*ys[42]*gab1;
    float bI  = p[36]*ys[39]*ys[42];
    float bP  = p[64]*ys[64]*ys[42];
    float sum_p85c = ys[43] + ys[44] + ys[45] + ys[46] + ys[67];
    float kunb = p[37];
    d[42] = -bE - bH2 - bH3 - bI - bP + kunb*sum_p85c;
    d[43] = bE  - kunb*ys[43];
    d[44] = bH2 - kunb*ys[44];
    d[45] = bH3 - kunb*ys[45];
    d[46] = bI  - kunb*ys[46];
    d[67] = bP  - kunb*ys[67];
    float pi3k_act = p[38]*sum_p85c*ys[47] + p[67]*ys[15]*ys[47];
    float mtor_fb  = p[39]*ys[56]*ys[48];
    d[47] = -pi3k_act + mtor_fb;
    d[48] =  pi3k_act - mtor_fb;
    float pip_fwd = p[40]*ys[48]*ys[49];
    float pip_rev = p[41]*ys[51]*ys[50];
    d[49] = -pip_fwd + pip_rev;
    d[50] =  pip_fwd - pip_rev;
    d[51] = p[69]*ys[28] - p[25]*ys[51];
    float akt_fwd = p[42]*ys[50]*ys[53];
    float akt_rev = p[43]*ys[52];
    d[52] =  akt_fwd - akt_rev;
    d[53] = -akt_fwd + akt_rev;
    float tsc = p[73]*ys[52]*ys[54];
    d[54] = -tsc;
    d[55] =  tsc - p[25]*ys[55];
    float mtor_fwd = p[44]*ys[52]*ys[57];
    float mtor_rev = p[45]*ys[56];
    d[56] =  mtor_fwd - mtor_rev;
    d[57] = -mtor_fwd + mtor_rev;
    float ebp_fwd = p[46]*ys[56]*ys[58];
    float ebp_rev = p[47]*ys[59];
    d[58] = -ebp_fwd + ebp_rev;
    d[59] =  ebp_fwd - ebp_rev;
    float ksr_fwd = p[48]*ys[19]*ys[62]*tram_ksr;
    float ksr_rev = p[49]*ys[60];
    d[60] =  ksr_fwd - ksr_rev;
    d[62] = -ksr_fwd + ksr_rev;
    d[63] = -p[63]*ys[63];
    d[64] =  p[63]*ys[63] - p[6]*ys[64];
    float s6_fwd = p[65]*ys[56]*ys[65];
    float rsk    = p[74]*ys[28]*ys[65];
    float s6_rev = p[66]*ys[66];
    d[65] = -s6_fwd + s6_rev - rsk;
    d[66] =  s6_fwd - s6_rev + rsk;
}

__global__ __launch_bounds__(THREADS, 4)
void mapk_rhs_kernel(const float* __restrict__ y, const float* __restrict__ params,
                     float* __restrict__ out, int n) {
    // Per-warp float4 tile, column-major with stride 33 (conflict-free).
    __shared__ float4 stage[WARPS_PER_BLOCK][NF4 * COLSTRIDE];
    __shared__ int sFast;

    const int tid  = threadIdx.x;
    const int lane = tid & 31;
    const int warp = tid >> 5;

    // ---- per-BLOCK param verification (75 lane-loads/block, shared broadcast) ----
    if (tid == 0) sFast = 1;
    __syncthreads();
    if (tid < 75) {
        if (__ldg(&params[tid]) != c_p[tid]) sFast = 0;   // benign race: all write 0
    }
    __syncthreads();
    const bool fast = (sFast != 0);

    const int rowStart = blockIdx.x * THREADS + warp * 32;
    if (rowStart >= n) return;
    const int rowsHere = min(32, n - rowStart);

    float4* sm = stage[warp];

    if (fast && rowsHere == 32) {
        const float4* gsrc = reinterpret_cast<const float4*>(y) + (size_t)rowStart * NF4;

        // ---- Phase 1: coalesced LDG.128 -> transposed smem tile ----
        #pragma unroll
        for (int j = 0; j < NF4; j++) {
            int i = j * 32 + lane;          // f4 index within warp tile
            int r = i / NF4;
            int c = i - r * NF4;
            float4 v = __ldg(&gsrc[i]);
            v.x = fmaxf(v.x, 0.0f);
            v.y = fmaxf(v.y, 0.0f);
            v.z = fmaxf(v.z, 0.0f);
            v.w = fmaxf(v.w, 0.0f);
            sm[c * COLSTRIDE + r] = v;
        }
        __syncwarp();

        // ---- Phase 2: each thread owns row = lane; conflict-free smem access.
        //      d[] scoped HERE and never passed to a non-inlined callee, so it
        //      stays register-resident (the R15 local-memory trap). ----
        {
            float ys[NSTATE];
            float4* ysv = reinterpret_cast<float4*>(ys);
            #pragma unroll
            for (int c = 0; c < NF4; c++) ysv[c] = sm[c * COLSTRIDE + lane];

            float d[NSTATE];
            compute_rhs_const(ys, d);

            const float4* dv = reinterpret_cast<const float4*>(d);
            #pragma unroll
            for (int c = 0; c < NF4; c++) sm[c * COLSTRIDE + lane] = dv[c];
        }
        __syncwarp();

        // ---- Phase 3: transposed smem tile -> coalesced streaming STG.128 ----
        float4* gdst = reinterpret_cast<float4*>(out) + (size_t)rowStart * NF4;
        #pragma unroll
        for (int j = 0; j < NF4; j++) {
            int i = j * 32 + lane;
            int r = i / NF4;
            int c = i - r * NF4;
            __stcs(&gdst[i], sm[c * COLSTRIDE + r]);
        }
    } else if (lane < rowsHere) {
        // ---- Tail / generic fallback: direct per-row float4 access ----
        const int row = rowStart + lane;
        const float4* yv = reinterpret_cast<const float4*>(y) + (size_t)row * NF4;
        float ys[NSTATE];
        float4* ysv = reinterpret_cast<float4*>(ys);
        #pragma unroll
        for (int c = 0; c < NF4; c++) {
            float4 v = __ldg(&yv[c]);
            v.x = fmaxf(v.x, 0.0f);
            v.y = fmaxf(v.y, 0.0f);
            v.z = fmaxf(v.z, 0.0f);
            v.w = fmaxf(v.w, 0.0f);
            ysv[c] = v;
        }
        float d[NSTATE];
        if (fast) compute_rhs_const(ys, d);
        else      compute_rhs_gen(params, ys, d);
        float4* ov = reinterpret_cast<float4*>(out) + (size_t)row * NF4;
        const float4* dv = reinterpret_cast<const float4*>(d);
        #pragma unroll
        for (int c = 0; c < NF4; c++) ov[c] = dv[c];
    }
}

extern "C" void kernel_launch(void* const* d_in, const int* in_sizes, int n_in,
                              void* d_out, int out_size) {
    // inputs per metadata order: t (1), y (B*68), params (75)
    const float* y      = (const float*)d_in[1];
    const float* params = (const float*)d_in[2];
    float* out = (float*)d_out;

    int n = in_sizes[1] / NSTATE;   // number of rows (B)

    int blocks = (n + THREADS - 1) / THREADS;
    mapk_rhs_kernel<<<blocks, THREADS>>>(y, params, out, n);
}

// round 17
// speedup vs baseline: 1.4311x; 1.0046x over previous
#include <cuda_runtime.h>

#define EPS 1e-10f
#define NSTATE 68
#define NF4 17                      // 68 floats = 17 float4
#define COLSTRIDE 33                // 33 % 8 == 1 -> conflict-free bank walk
#define WARPS_PER_BLOCK 4
#define THREADS (WARPS_PER_BLOCK * 32)

// Parameters baked into the constant bank at compile time (verified at runtime,
// once per block, overlapped with the phase-1 tile loads). [0..74] = PARAM_DEFAULTS.
// [75..80] = derived constants (fp32-folded identically to the runtime fallback).
__constant__ float c_p[81] = {
    0.1f,0.05f,0.2f,0.1f,0.1f,0.1f,0.01f,0.01f,0.05f,0.01f,
    0.1f,0.01f,0.1f,0.01f,0.01f,0.01f,
    0.01f,0.01f,0.05f,0.01f,0.01f,0.01f,0.1f,0.1f,
    0.01f,0.01f,0.01f,0.1f,0.1f,0.05f,0.01f,
    0.05f,0.05f,0.1f,0.1f,0.1f,0.1f,
    0.05f,0.1f,0.01f,0.1f,0.05f,0.1f,0.01f,
    0.05f,0.05f,0.1f,0.05f,0.1f,0.05f,0.1f,0.1f,
    0.05f,0.1f,1.0f,1.0f,1.0f,1.0f,0.1f,0.05f,
    0.1f,1.0f,1.0f,0.05f,0.1f,0.1f,0.05f,
    0.05f,0.02f,0.01f,0.02f,0.02f,
    0.01f,0.05f,0.03f,
    // derived:
    0.1f * 1.0f / (1.0f + 1.0f + 1e-10f),   // 75 kBRAF_eff = 0.05
    1.0f / (1.0f + 0.1f + 1e-10f),          // 76 tram_ksr (Tram = 0.1)
    0.1f / (0.1f + 1e-10f),                 // 77 kmDuspRatio
    0.1f / (0.1f + 1e-10f),                 // 78 kmSprtyRatio
    0.1f * 1.0f,                            // 79 kDimVem
    0.1f * 1.0f                             // 80 kParaVem
};

// ---- FAST PATH: params from the statically-initialized constant bank ----
__device__ __forceinline__ void compute_rhs_const(const float* ys, float* d) {
    const float ka1 = c_p[0], kr1 = c_p[1], kc1 = c_p[2];
    const float kBRAF_eff    = c_p[75];
    const float tram_ksr     = c_p[76];
    const float kmDuspRatio  = c_p[77];
    const float kmSprtyRatio = c_p[78];
    const float kDimVem      = c_p[79];
    const float kParaVem     = c_p[80];

    d[0] = -ka1*ys[0] + kr1*ys[1];
    d[1] =  ka1*ys[0] - kr1*ys[1] - kc1*ys[1];
    d[2] =  kc1*ys[1] - c_p[6]*ys[2] - c_p[7]*ys[28]*ys[2];
    d[3] = -c_p[31]*ys[3] + kr1*ys[4];
    d[4] =  c_p[31]*ys[3] - kr1*ys[4] - kc1*ys[4];
    d[5] =  kc1*ys[4] - c_p[6]*ys[5] - c_p[7]*ys[28]*ys[5];
    d[6] = -c_p[32]*ys[6] + kr1*ys[7];
    d[7] =  c_p[32]*ys[6] - kr1*ys[7] - kc1*ys[7];
    d[8] =  kc1*ys[7] - c_p[6]*ys[8] - c_p[7]*ys[28]*ys[8];

    float a29 = ka1*ys[2]*ys[9];
    d[9]  = -a29;
    d[10] =  a29 - c_p[8]*ys[11]*ys[10];
    d[11] = -c_p[9]*ys[10]*ys[11];
    d[12] =  c_p[10]*ys[10]*ys[2] - c_p[11]*ys[26]*ys[12];
    d[13] =  c_p[12]*ys[12]*ys[10] - c_p[13]*ys[24]*ys[13];
    float s14 = ka1*ys[13]*ys[14];
    d[14] = -s14;
    d[15] =  s14;
    float s16 = ka1*ys[13]*ys[16];
    d[16] = -s16;
    d[17] =  s16;
    float s18 = ka1*ys[13]*ys[18];
    float s19 = ka1*ys[19]*ys[20];
    d[18] = -s18;
    d[19] =  s18 - s19;
    d[20] = -s19;

    float paradox   = kParaVem * ys[61];
    float akt_craf  = c_p[70]*ys[52]*ys[21];
    float dimF      = kDimVem*ys[24]*ys[21];
    float dimD      = c_p[59]*ys[61];
    float craf_fwd  = c_p[3]*ys[19]*ys[21];
    float craf_rev  = c_p[14]*ys[28]*ys[22];
    float craf_deg  = c_p[15]*ys[22]*ys[35];
    float braf_act  = kBRAF_eff*ys[23]*ys[19];
    d[21] = -craf_fwd + craf_rev + craf_deg - dimF + dimD - akt_craf;
    d[22] =  craf_fwd - craf_rev - craf_deg + paradox;
    d[23] = -braf_act - dimF + dimD;
    d[24] =  braf_act - c_p[20]*ys[24] - dimF + dimD;
    d[61] =  dimF - dimD - c_p[15]*ys[61]*ys[35];

    float raf_to_mek = c_p[4]*ys[22] + c_p[50]*ys[24] + c_p[51]*ys[22];
    float ksr_to_mek = c_p[52]*ys[60];
    float mek_fwd    = (raf_to_mek + ksr_to_mek)*ys[25];
    float mek_rev    = c_p[16]*ys[28]*ys[26];
    float mek_deg    = c_p[17]*ys[26]*ys[34];
    d[25] = -mek_fwd + mek_rev + mek_deg;
    d[26] =  mek_fwd - mek_rev - mek_deg;
    float erk_fwd = c_p[5]*ys[26]*ys[27];
    float erk_bk  = c_p[18]*ys[30]*ys[28] + c_p[19]*ys[28]*ys[33] + c_p[29]*ys[30]*ys[28];
    d[27] = -erk_fwd + erk_bk;
    d[28] =  erk_fwd - erk_bk;

    float denom_dusp = 1.0f + kmDuspRatio*ys[28];
    d[29] = c_p[27]*ys[28]/(denom_dusp + EPS) - c_p[21]*ys[29]*ys[36] - c_p[30]*ys[29]*ys[28];
    d[30] = -c_p[21]*ys[29]*ys[30];
    float denom_spry = 1.0f + kmSprtyRatio*ys[28];
    float spry_dn = c_p[24]*ys[31]*ys[32];
    d[31] = c_p[28]*ys[28]/(denom_spry + EPS) - spry_dn;
    d[32] = -spry_dn;
    d[33] = -c_p[19]*ys[28]*ys[33];
    d[34] = -mek_deg;
    d[35] = -craf_deg;
    d[36] = -c_p[21]*ys[29]*ys[36];

    d[37] = -ka1*ys[37] + kr1*ys[38];
    d[38] =  ka1*ys[37] - kr1*ys[38] - kc1*ys[38];
    d[39] =  kc1*ys[38] - c_p[7]*ys[28]*ys[39];
    float erk_irs = c_p[68]*ys[28]*ys[41];
    float s6k_irs = c_p[71]*ys[66]*ys[41];
    float irs_fwd = ka1*ys[2]*ys[40];
    d[40] = -irs_fwd + erk_irs + s6k_irs;
    d[41] =  irs_fwd - erk_irs - s6k_irs;

    float gab1 = 1.0f / (1.0f + c_p[72]*ys[28]);
    float bE  = c_p[33]*ys[2]*ys[42]*gab1;
    float bH2 = c_p[34]*ys[5]*ys[42]*gab1;
    float bH3 = c_p[35]*ys[8]*ys[42]*gab1;
    float bI  = c_p[36]*ys[39]*ys[42];
    float bP  = c_p[64]*ys[64]*ys[42];
    float sum_p85c = ys[43] + ys[44] + ys[45] + ys[46] + ys[67];
    float kunb = c_p[37];
    d[42] = -bE - bH2 - bH3 - bI - bP + kunb*sum_p85c;
    d[43] = bE  - kunb*ys[43];
    d[44] = bH2 - kunb*ys[44];
    d[45] = bH3 - kunb*ys[45];
    d[46] = bI  - kunb*ys[46];
    d[67] = bP  - kunb*ys[67];

    float pi3k_act = c_p[38]*sum_p85c*ys[47] + c_p[67]*ys[15]*ys[47];
    float mtor_fb  = c_p[39]*ys[56]*ys[48];
    d[47] = -pi3k_act + mtor_fb;
    d[48] =  pi3k_act - mtor_fb;
    float pip_fwd = c_p[40]*ys[48]*ys[49];
    float pip_rev = c_p[41]*ys[51]*ys[50];
    d[49] = -pip_fwd + pip_rev;
    d[50] =  pip_fwd - pip_rev;
    d[51] = c_p[69]*ys[28] - c_p[25]*ys[51];
    float akt_fwd = c_p[42]*ys[50]*ys[53];
    float akt_rev = c_p[43]*ys[52];
    d[52] =  akt_fwd - akt_rev;
    d[53] = -akt_fwd + akt_rev;
    float tsc = c_p[73]*ys[52]*ys[54];
    d[54] = -tsc;
    d[55] =  tsc - c_p[25]*ys[55];
    float mtor_fwd = c_p[44]*ys[52]*ys[57];
    float mtor_rev = c_p[45]*ys[56];
    d[56] =  mtor_fwd - mtor_rev;
    d[57] = -mtor_fwd + mtor_rev;
    float ebp_fwd = c_p[46]*ys[56]*ys[58];
    float ebp_rev = c_p[47]*ys[59];
    d[58] = -ebp_fwd + ebp_rev;
    d[59] =  ebp_fwd - ebp_rev;

    float ksr_fwd = c_p[48]*ys[19]*ys[62]*tram_ksr;
    float ksr_rev = c_p[49]*ys[60];
    d[60] =  ksr_fwd - ksr_rev;
    d[62] = -ksr_fwd + ksr_rev;

    d[63] = -c_p[63]*ys[63];
    d[64] =  c_p[63]*ys[63] - c_p[6]*ys[64];

    float s6_fwd = c_p[65]*ys[56]*ys[65];
    float rsk    = c_p[74]*ys[28]*ys[65];
    float s6_rev = c_p[66]*ys[66];
    d[65] = -s6_fwd + s6_rev - rsk;
    d[66] =  s6_fwd - s6_rev + rsk;
}

// ---- GENERIC FALLBACK: params from global memory (taken only if params differ) ----
__device__ __noinline__ void compute_rhs_gen(const float* __restrict__ p,
                                             const float* ys, float* d) {
    const float ic50n     = __powf(p[61], p[62]);
    const float vemn      = __powf(p[57], p[62]);
    const float kBRAF_eff = p[0] * ic50n / (ic50n + vemn + EPS);
    const float ktn       = __powf(p[55], p[56]);
    const float tn        = __powf(p[53], p[56]);
    const float tram_ksr  = ktn / (ktn + tn + EPS);
    const float kmDuspRatio  = p[27] / (p[22] + EPS);
    const float kmSprtyRatio = p[28] / (p[23] + EPS);
    const float kDimVem   = p[58] * p[57];
    const float kParaVem  = p[60] * p[57];

    d[0] = -p[0]*ys[0] + p[1]*ys[1];
    d[1] =  p[0]*ys[0] - p[1]*ys[1] - p[2]*ys[1];
    d[2] =  p[2]*ys[1] - p[6]*ys[2] - p[7]*ys[28]*ys[2];
    d[3] = -p[31]*ys[3] + p[1]*ys[4];
    d[4] =  p[31]*ys[3] - p[1]*ys[4] - p[2]*ys[4];
    d[5] =  p[2]*ys[4] - p[6]*ys[5] - p[7]*ys[28]*ys[5];
    d[6] = -p[32]*ys[6] + p[1]*ys[7];
    d[7] =  p[32]*ys[6] - p[1]*ys[7] - p[2]*ys[7];
    d[8] =  p[2]*ys[7] - p[6]*ys[8] - p[7]*ys[28]*ys[8];
    float a29 = p[0]*ys[2]*ys[9];
    d[9]  = -a29;
    d[10] =  a29 - p[8]*ys[11]*ys[10];
    d[11] = -p[9]*ys[10]*ys[11];
    d[12] =  p[10]*ys[10]*ys[2] - p[11]*ys[26]*ys[12];
    d[13] =  p[12]*ys[12]*ys[10] - p[13]*ys[24]*ys[13];
    float s14 = p[0]*ys[13]*ys[14];
    d[14] = -s14;  d[15] = s14;
    float s16 = p[0]*ys[13]*ys[16];
    d[16] = -s16;  d[17] = s16;
    float s18 = p[0]*ys[13]*ys[18];
    float s19 = p[0]*ys[19]*ys[20];
    d[18] = -s18;  d[19] = s18 - s19;  d[20] = -s19;
    float paradox   = kParaVem * ys[61];
    float akt_craf  = p[70]*ys[52]*ys[21];
    float dimF      = kDimVem*ys[24]*ys[21];
    float dimD      = p[59]*ys[61];
    float craf_fwd  = p[3]*ys[19]*ys[21];
    float craf_rev  = p[14]*ys[28]*ys[22];
    float craf_deg  = p[15]*ys[22]*ys[35];
    float braf_act  = kBRAF_eff*ys[23]*ys[19];
    d[21] = -craf_fwd + craf_rev + craf_deg - dimF + dimD - akt_craf;
    d[22] =  craf_fwd - craf_rev - craf_deg + paradox;
    d[23] = -braf_act - dimF + dimD;
    d[24] =  braf_act - p[20]*ys[24] - dimF + dimD;
    d[61] =  dimF - dimD - p[15]*ys[61]*ys[35];
    float raf_to_mek = p[4]*ys[22] + p[50]*ys[24] + p[51]*ys[22];
    float ksr_to_mek = p[52]*ys[60];
    float mek_fwd    = (raf_to_mek + ksr_to_mek)*ys[25];
    float mek_rev    = p[16]*ys[28]*ys[26];
    float mek_deg    = p[17]*ys[26]*ys[34];
    d[25] = -mek_fwd + mek_rev + mek_deg;
    d[26] =  mek_fwd - mek_rev - mek_deg;
    float erk_fwd = p[5]*ys[26]*ys[27];
    float erk_bk  = p[18]*ys[30]*ys[28] + p[19]*ys[28]*ys[33] + p[29]*ys[30]*ys[28];
    d[27] = -erk_fwd + erk_bk;
    d[28] =  erk_fwd - erk_bk;
    float denom_dusp = 1.0f + kmDuspRatio*ys[28];
    d[29] = p[27]*ys[28]/(denom_dusp + EPS) - p[21]*ys[29]*ys[36] - p[30]*ys[29]*ys[28];
    d[30] = -p[21]*ys[29]*ys[30];
    float denom_spry = 1.0f + kmSprtyRatio*ys[28];
    float spry_dn = p[24]*ys[31]*ys[32];
    d[31] = p[28]*ys[28]/(denom_spry + EPS) - spry_dn;
    d[32] = -spry_dn;
    d[33] = -p[19]*ys[28]*ys[33];
    d[34] = -mek_deg;
    d[35] = -craf_deg;
    d[36] = -p[21]*ys[29]*ys[36];
    d[37] = -p[0]*ys[37] + p[1]*ys[38];
    d[38] =  p[0]*ys[37] - p[1]*ys[38] - p[2]*ys[38];
    d[39] =  p[2]*ys[38] - p[7]*ys[28]*ys[39];
    float erk_irs = p[68]*ys[28]*ys[41];
    float s6k_irs = p[71]*ys[66]*ys[41];
    float irs_fwd = p[0]*ys[2]*ys[40];
    d[40] = -irs_fwd + erk_irs + s6k_irs;
    d[41] =  irs_fwd - erk_irs - s6k_irs;
    float gab1 = 1.0f / (1.0f + p[72]*ys[28]);
    float bE  = p[33]*ys[2]*ys[42]*gab1;
    float bH2 = p[34]*ys[5]*ys[42]*gab1;
    float bH3 = p[35]*ys[8]*ys[42]*gab1;
    float bI  = p[36]*ys[39]*ys[42];
    float bP  = p[64]*ys[64]*ys[42];
    float sum_p85c = ys[43] + ys[44] + ys[45] + ys[46] + ys[67];
    float kunb = p[37];
    d[42] = -bE - bH2 - bH3 - bI - bP + kunb*sum_p85c;
    d[43] = bE  - kunb*ys[43];
    d[44] = bH2 - kunb*ys[44];
    d[45] = bH3 - kunb*ys[45];
    d[46] = bI  - kunb*ys[46];
    d[67] = bP  - kunb*ys[67];
    float pi3k_act = p[38]*sum_p85c*ys[47] + p[67]*ys[15]*ys[47];
    float mtor_fb  = p[39]*ys[56]*ys[48];
    d[47] = -pi3k_act + mtor_fb;
    d[48] =  pi3k_act - mtor_fb;
    float pip_fwd = p[40]*ys[48]*ys[49];
    float pip_rev = p[41]*ys[51]*ys[50];
    d[49] = -pip_fwd + pip_rev;
    d[50] =  pip_fwd - pip_rev;
    d[51] = p[69]*ys[28] - p[25]*ys[51];
    float akt_fwd = p[42]*ys[50]*ys[53];
    float akt_rev = p[43]*ys[52];
    d[52] =  akt_fwd - akt_rev;
    d[53] = -akt_fwd + akt_rev;
    float tsc = p[73]*ys[52]*ys[54];
    d[54] = -tsc;
    d[55] =  tsc - p[25]*ys[55];
    float mtor_fwd = p[44]*ys[52]*ys[57];
    float mtor_rev = p[45]*ys[56];
    d[56] =  mtor_fwd - mtor_rev;
    d[57] = -mtor_fwd + mtor_rev;
    float ebp_fwd = p[46]*ys[56]*ys[58];
    float ebp_rev = p[47]*ys[59];
    d[58] = -ebp_fwd + ebp_rev;
    d[59] =  ebp_fwd - ebp_rev;
    float ksr_fwd = p[48]*ys[19]*ys[62]*tram_ksr;
    float ksr_rev = p[49]*ys[60];
    d[60] =  ksr_fwd - ksr_rev;
    d[62] = -ksr_fwd + ksr_rev;
    d[63] = -p[63]*ys[63];
    d[64] =  p[63]*ys[63] - p[6]*ys[64];
    float s6_fwd = p[65]*ys[56]*ys[65];
    float rsk    = p[74]*ys[28]*ys[65];
    float s6_rev = p[66]*ys[66];
    d[65] = -s6_fwd + s6_rev - rsk;
    d[66] =  s6_fwd - s6_rev + rsk;
}

__global__ __launch_bounds__(THREADS, 4)
void mapk_rhs_kernel(const float* __restrict__ y, const float* __restrict__ params,
                     float* __restrict__ out, int n) {
    // Per-warp float4 tile, column-major with stride 33 (conflict-free).
    __shared__ float4 stage[WARPS_PER_BLOCK][NF4 * COLSTRIDE];
    __shared__ int sFast;

    const int tid  = threadIdx.x;
    const int lane = tid & 31;
    const int warp = tid >> 5;

    if (tid == 0) sFast = 1;
    __syncthreads();                        // cheap: no memory deps yet

    const int rowStart = blockIdx.x * THREADS + warp * 32;
    const int rowsHere = (rowStart < n) ? min(32, n - rowStart) : 0;
    const bool fullTile = (rowsHere == 32);

    float4* sm = stage[warp];

    // ---- Phase 1: tile loads issued FIRST (front-batched, high MLP) ----
    if (fullTile) {
        const float4* gsrc = reinterpret_cast<const float4*>(y) + (size_t)rowStart * NF4;
        #pragma unroll
        for (int j = 0; j < NF4; j++) {
            int i = j * 32 + lane;          // f4 index within warp tile
            int r = i / NF4;
            int c = i - r * NF4;
            float4 v = __ldg(&gsrc[i]);
            v.x = fmaxf(v.x, 0.0f);
            v.y = fmaxf(v.y, 0.0f);
            v.z = fmaxf(v.z, 0.0f);
            v.w = fmaxf(v.w, 0.0f);
            sm[c * COLSTRIDE + r] = v;
        }
    } else if (lane < rowsHere) {
        const float4* yv = reinterpret_cast<const float4*>(y) + (size_t)(rowStart + lane) * NF4;
        #pragma unroll
        for (int c = 0; c < NF4; c++) {
            float4 v = __ldg(&yv[c]);
            v.x = fmaxf(v.x, 0.0f);
            v.y = fmaxf(v.y, 0.0f);
            v.z = fmaxf(v.z, 0.0f);
            v.w = fmaxf(v.w, 0.0f);
            sm[c * COLSTRIDE + lane] = v;
        }
    }

    // ---- Param verification, latency hidden under the tile loads above ----
    if (tid < 75) {
        if (__ldg(&params[tid]) != c_p[tid]) sFast = 0;   // benign race: all write 0
    }
    __syncthreads();                        // covers smem tiles + sFast
    const bool fast = (sFast != 0);

    if (rowsHere == 0) return;

    // ---- Phase 2: DISJOINT branches, each with its own scoped ys[]/d[].
    //      The fast branch never touches the noinline callee, so its arrays
    //      stay register-resident (avoids the R15 local-memory demotion). ----
    if (fast) {
        if (lane < rowsHere) {
            float ys[NSTATE];
            float4* ysv = reinterpret_cast<float4*>(ys);
            #pragma unroll
            for (int c = 0; c < NF4; c++) ysv[c] = sm[c * COLSTRIDE + lane];

            float d[NSTATE];
            compute_rhs_const(ys, d);

            const float4* dv = reinterpret_cast<const float4*>(d);
            #pragma unroll
            for (int c = 0; c < NF4; c++) sm[c * COLSTRIDE + lane] = dv[c];
        }
    } else {
        if (lane < rowsHere) {
            float ys2[NSTATE];
            float4* ysv2 = reinterpret_cast<float4*>(ys2);
            #pragma unroll
            for (int c = 0; c < NF4; c++) ysv2[c] = sm[c * COLSTRIDE + lane];

            float d2[NSTATE];
            compute_rhs_gen(params, ys2, d2);

            const float4* dv2 = reinterpret_cast<const float4*>(d2);
            #pragma unroll
            for (int c = 0; c < NF4; c++) sm[c * COLSTRIDE + lane] = dv2[c];
        }
    }
    __syncwarp();

    // ---- Phase 3: coalesced stores from the tile ----
    if (fullTile) {
        float4* gdst = reinterpret_cast<float4*>(out) + (size_t)rowStart * NF4;
        #pragma unroll
        for (int j = 0; j < NF4; j++) {
            int i = j * 32 + lane;
            int r = i / NF4;
            int c = i - r * NF4;
            gdst[i] = sm[c * COLSTRIDE + r];
        }
    } else if (lane < rowsHere) {
        float4* ov = reinterpret_cast<float4*>(out) + (size_t)(rowStart + lane) * NF4;
        #pragma unroll
        for (int c = 0; c < NF4; c++) ov[c] = sm[c * COLSTRIDE + lane];
    }
}

extern "C" void kernel_launch(void* const* d_in, const int* in_sizes, int n_in,
                              void* d_out, int out_size) {
    // inputs per metadata order: t (1), y (B*68), params (75)
    const float* y      = (const float*)d_in[1];
    const float* params = (const float*)d_in[2];
    float* out = (float*)d_out;

    int n = in_sizes[1] / NSTATE;   // number of rows (B)

    int blocks = (n + THREADS - 1) / THREADS;
    mapk_rhs_kernel<<<blocks, THREADS>>>(y, params, out, n);
}